// round 1
// baseline (speedup 1.0000x reference)
#include <cuda_runtime.h>
#include <math_constants.h>

// Problem constants
constexpr int BB  = 2;
constexpr int NN  = 2048;
constexpr int DD  = 1024;
constexpr int HH  = 16;
constexpr int RR  = 32;
constexpr int DK  = 64;
constexpr int HR  = HH * RR;      // 512
constexpr int BN  = BB * NN;      // 4096

// Scratch (device globals; no allocation allowed)
__device__ float g_wq_eff[DD * HR];     // [d][h*R+r]
__device__ float g_wk_eff[DD * HR];
__device__ float g_q[BN * HR];          // [b*n][h*R+r]
__device__ float g_k[BN * HR];
__device__ float g_v[BN * DD];          // [b*n][h*DK+d]
__device__ float g_z[BN * DD];          // [b*n][h*DK+d]

// ---------------------------------------------------------------------------
// Effective low-rank weights: Weff[d, h*R+r] = sum_kk W[(h*64+kk), d] * U[kk, r]
// block: 256 threads over hr (x), grid: (HR/256, DD)
// ---------------------------------------------------------------------------
__global__ void weff_kernel(const float* __restrict__ Wq,
                            const float* __restrict__ Wk,
                            const float* __restrict__ U,
                            float* __restrict__ wq_eff,
                            float* __restrict__ wk_eff)
{
    int hr = blockIdx.x * blockDim.x + threadIdx.x;   // 0..511
    int d  = blockIdx.y;                              // 0..1023
    int h  = hr >> 5;
    int r  = hr & 31;
    float sq = 0.f, sk = 0.f;
#pragma unroll 8
    for (int kk = 0; kk < DK; kk++) {
        float u = U[kk * RR + r];                      // coalesced over r
        sq = fmaf(Wq[(size_t)(h * DK + kk) * DD + d], u, sq);  // broadcast within h-group
        sk = fmaf(Wk[(size_t)(h * DK + kk) * DD + d], u, sk);
    }
    wq_eff[(size_t)d * HR + hr] = sq;                  // coalesced
    wk_eff[(size_t)d * HR + hr] = sk;
}

// ---------------------------------------------------------------------------
// Tiled SGEMM, 128x128x8, 256 threads, 8x8 per thread.
// BT=false: C[M,N] = A[M,K] @ B[K,N]   (B row-major [K,N])
// BT=true : C[M,N] = A[M,K] @ B^T      (B row-major [N,K])
// All dims assumed multiples of the tile (true here).
// ---------------------------------------------------------------------------
template <bool BT>
__global__ __launch_bounds__(256) void sgemm_kernel(
    const float* __restrict__ A, const float* __restrict__ B,
    float* __restrict__ C, int M, int N, int K)
{
    __shared__ float As[8][128];
    __shared__ float Bs[8][128];

    int tid  = threadIdx.x;
    int bcol = blockIdx.x * 128;
    int brow = blockIdx.y * 128;
    int tx = tid & 15;            // 0..15 -> 8 cols each
    int ty = tid >> 4;            // 0..15 -> 8 rows each

    int lrow = tid >> 1;          // 0..127 (A / B^T loads)
    int lc4  = (tid & 1) * 4;     // 0 or 4
    int bnrow = tid >> 5;         // 0..7   (B NN loads)
    int bnc4  = (tid & 31) * 4;   // 0..124

    float acc[8][8];
#pragma unroll
    for (int i = 0; i < 8; i++)
#pragma unroll
        for (int j = 0; j < 8; j++) acc[i][j] = 0.f;

    const float* Aptr = A + (size_t)(brow + lrow) * K + lc4;
    const float* Bptr = BT ? (B + (size_t)(bcol + lrow) * K + lc4)
                           : (B + (size_t)bnrow * N + bcol + bnc4);

    for (int k0 = 0; k0 < K; k0 += 8) {
        float4 av = *(const float4*)(Aptr + k0);
        float4 bv;
        if (BT) bv = *(const float4*)(Bptr + k0);
        else    bv = *(const float4*)(Bptr + (size_t)k0 * N);

        __syncthreads();
        As[lc4 + 0][lrow] = av.x; As[lc4 + 1][lrow] = av.y;
        As[lc4 + 2][lrow] = av.z; As[lc4 + 3][lrow] = av.w;
        if (BT) {
            Bs[lc4 + 0][lrow] = bv.x; Bs[lc4 + 1][lrow] = bv.y;
            Bs[lc4 + 2][lrow] = bv.z; Bs[lc4 + 3][lrow] = bv.w;
        } else {
            *(float4*)&Bs[bnrow][bnc4] = bv;
        }
        __syncthreads();

#pragma unroll
        for (int kk = 0; kk < 8; kk++) {
            float a[8], b[8];
#pragma unroll
            for (int i = 0; i < 8; i++) a[i] = As[kk][ty * 8 + i];
#pragma unroll
            for (int j = 0; j < 8; j++) b[j] = Bs[kk][tx * 8 + j];
#pragma unroll
            for (int i = 0; i < 8; i++)
#pragma unroll
                for (int j = 0; j < 8; j++)
                    acc[i][j] = fmaf(a[i], b[j], acc[i][j]);
        }
    }

#pragma unroll
    for (int i = 0; i < 8; i++) {
        float* cp = C + (size_t)(brow + ty * 8 + i) * N + bcol + tx * 8;
        *(float4*)(cp + 0) = make_float4(acc[i][0], acc[i][1], acc[i][2], acc[i][3]);
        *(float4*)(cp + 4) = make_float4(acc[i][4], acc[i][5], acc[i][6], acc[i][7]);
    }
}

// ---------------------------------------------------------------------------
// Flash attention with ALiBi + additive mask.
// grid (N/128, H, B); 128 threads; thread = one query row.
// q,k layout [b][n][h][R]; v,z layout [b][n][h][DK].
// ---------------------------------------------------------------------------
__global__ __launch_bounds__(128) void attn_kernel(
    const float* __restrict__ q, const float* __restrict__ k,
    const float* __restrict__ v, const float* __restrict__ mask,
    const int* __restrict__ rbt, float* __restrict__ z)
{
    constexpr int CH = 16;                 // kv chunk
    __shared__ float Ks[CH][RR];           // 2 KB
    __shared__ float Vs[CH][DK];           // 4 KB

    int b = blockIdx.z, h = blockIdx.y;
    int t = threadIdx.x;
    int qi = blockIdx.x * 128 + t;

    float slope = exp2f(-0.5f * (float)(h + 1));   // ALiBi slope for H=16
    int   Ttok  = rbt[0];
    // dist = max(j - (qi + Ttok - N), 0)
    float dbase = (float)(-(qi + Ttok - NN));

    float qv[RR];
    const float* qp = q + ((size_t)(b * NN + qi) * HH + h) * RR;
#pragma unroll
    for (int r4 = 0; r4 < RR / 4; r4++)
        ((float4*)qv)[r4] = ((const float4*)qp)[r4];

    float acc[DK];
#pragma unroll
    for (int d = 0; d < DK; d++) acc[d] = 0.f;
    float mrow = -CUDART_INF_F, lsum = 0.f;

    const float* mbase = mask + (size_t)qi * NN;   // mask is [1,1,N,N]

#pragma unroll 1
    for (int k0 = 0; k0 < NN; k0 += CH) {
        __syncthreads();
        {   // cooperative loads: K chunk 16x32 (1 float4/thread), V chunk 16x64 (2/thread)
            int row = t >> 3, c4 = (t & 7) * 4;
            *(float4*)&Ks[row][c4] =
                *(const float4*)&k[((size_t)(b * NN + k0 + row) * HH + h) * RR + c4];
#pragma unroll
            for (int i = 0; i < 2; i++) {
                int idx = t + i * 128;
                int vr = idx >> 4, vc4 = (idx & 15) * 4;
                *(float4*)&Vs[vr][vc4] =
                    *(const float4*)&v[((size_t)(b * NN + k0 + vr) * HH + h) * DK + vc4];
            }
        }
        __syncthreads();

        float s[CH];
#pragma unroll
        for (int j4 = 0; j4 < CH / 4; j4++)       // preload mask row chunk into s[]
            ((float4*)s)[j4] = ((const float4*)(mbase + k0))[j4];

        float cmax = -CUDART_INF_F;
#pragma unroll
        for (int j = 0; j < CH; j++) {
            float dot = 0.f;
#pragma unroll
            for (int r = 0; r < RR; r++) dot = fmaf(qv[r], Ks[j][r], dot);
            float dist = fmaxf((float)(k0 + j) + dbase, 0.f);
            s[j] = fmaf(dot, 0.125f, s[j]) - slope * dist;   // scale = 1/sqrt(64)
            cmax = fmaxf(cmax, s[j]);
        }

        float mnew  = fmaxf(mrow, cmax);
        float scale = __expf(mrow - mnew);        // exp(-inf)=0 on first chunk
        lsum *= scale;
#pragma unroll
        for (int d = 0; d < DK; d++) acc[d] *= scale;
#pragma unroll
        for (int j = 0; j < CH; j++) {
            float p = __expf(s[j] - mnew);
            lsum += p;
#pragma unroll
            for (int d = 0; d < DK; d++) acc[d] = fmaf(p, Vs[j][d], acc[d]);
        }
        mrow = mnew;
    }

    float inv = 1.f / lsum;
    float* zp = z + ((size_t)(b * NN + qi) * HH + h) * DK;
#pragma unroll
    for (int d = 0; d < DK; d++) acc[d] *= inv;
#pragma unroll
    for (int d4 = 0; d4 < DK / 4; d4++)
        ((float4*)zp)[d4] = ((float4*)acc)[d4];
}

// ---------------------------------------------------------------------------
extern "C" void kernel_launch(void* const* d_in, const int* in_sizes, int n_in,
                              void* d_out, int out_size)
{
    const float* x    = (const float*)d_in[0];
    const float* mask = (const float*)d_in[1];
    const float* Wq   = (const float*)d_in[2];
    const float* Wk   = (const float*)d_in[3];
    const float* Wv   = (const float*)d_in[4];
    const float* U    = (const float*)d_in[5];
    const float* Wp   = (const float*)d_in[6];
    const int*   rbt  = (const int*)d_in[7];
    float* out = (float*)d_out;
    (void)in_sizes; (void)n_in; (void)out_size;

    float *wq_eff, *wk_eff, *qb, *kb, *vb, *zb;
    cudaGetSymbolAddress((void**)&wq_eff, g_wq_eff);
    cudaGetSymbolAddress((void**)&wk_eff, g_wk_eff);
    cudaGetSymbolAddress((void**)&qb, g_q);
    cudaGetSymbolAddress((void**)&kb, g_k);
    cudaGetSymbolAddress((void**)&vb, g_v);
    cudaGetSymbolAddress((void**)&zb, g_z);

    // 1. effective low-rank weights
    weff_kernel<<<dim3(HR / 256, DD), 256>>>(Wq, Wk, U, wq_eff, wk_eff);

    // 2. q = x @ Wq_eff, k = x @ Wk_eff   [4096,1024]@[1024,512]
    sgemm_kernel<false><<<dim3(HR / 128, BN / 128), 256>>>(x, wq_eff, qb, BN, HR, DD);
    sgemm_kernel<false><<<dim3(HR / 128, BN / 128), 256>>>(x, wk_eff, kb, BN, HR, DD);

    // 3. v = x @ Wv^T   [4096,1024]@[1024,1024]^T
    sgemm_kernel<true><<<dim3(DD / 128, BN / 128), 256>>>(x, Wv, vb, BN, DD, DD);

    // 4. flash attention with ALiBi + mask
    attn_kernel<<<dim3(NN / 128, HH, BB), 128>>>(qb, kb, vb, mask, rbt, zb);

    // 5. out = z @ Wproj^T
    sgemm_kernel<true><<<dim3(DD / 128, BN / 128), 256>>>(zb, Wp, out, BN, DD, DD);
}

// round 6
// speedup vs baseline: 4.0025x; 4.0025x over previous
#include <cuda_runtime.h>
#include <math_constants.h>
#include <cstdint>

// Problem constants
constexpr int BB  = 2;
constexpr int NN  = 2048;
constexpr int DD  = 1024;
constexpr int HH  = 16;
constexpr int RR  = 32;
constexpr int DK  = 64;
constexpr int HR  = HH * RR;      // 512
constexpr int BN  = BB * NN;      // 4096

// Scratch (device globals; no allocation allowed)
__device__ float g_wqT[HR * DD];        // [hr][d]  K-major
__device__ float g_wkT[HR * DD];
__device__ float g_q[BN * HR];          // [b*n][h*R+r]
__device__ float g_k[BN * HR];
__device__ float g_v[BN * DD];          // [b*n][h*DK+d]
__device__ float g_z[BN * DD];          // [b*n][h*DK+d]

// ---------------------------------------------------------------------------
// helpers
// ---------------------------------------------------------------------------
__device__ __forceinline__ float f2tf32(float x) {
    float y; asm("cvt.rna.tf32.f32 %0, %1;" : "=f"(y) : "f"(x)); return y;
}
__device__ __forceinline__ uint32_t u2tf32(float x) {
    return __float_as_uint(f2tf32(x));
}

// D += A(16x8,row) * B(8x8,col)   tf32 inputs, f32 accum
__device__ __forceinline__ void mma_t32(float d[4], const uint32_t a[4],
                                        const uint32_t b[2]) {
    asm volatile(
        "mma.sync.aligned.m16n8k8.row.col.f32.tf32.tf32.f32 "
        "{%0,%1,%2,%3}, {%4,%5,%6,%7}, {%8,%9}, {%0,%1,%2,%3};"
        : "+f"(d[0]), "+f"(d[1]), "+f"(d[2]), "+f"(d[3])
        : "r"(a[0]), "r"(a[1]), "r"(a[2]), "r"(a[3]), "r"(b[0]), "r"(b[1]));
}

// ---------------------------------------------------------------------------
// tf32 HMMA GEMM: C[M,N] = A[M,K] @ B[N,K]^T  (both K-major row-major)
// grid (N/128, M/128), block 256 (8 warps), warp tile 32x64, K-chunk 32.
// ---------------------------------------------------------------------------
__global__ __launch_bounds__(256) void mma_gemm(
    const float* __restrict__ A, const float* __restrict__ B,
    float* __restrict__ C, int K, int ldc)
{
    __shared__ float As[128][36];
    __shared__ float Bs[128][36];

    const int t = threadIdx.x, wid = t >> 5, lane = t & 31;
    const int gr = lane >> 2, tq = lane & 3;
    const int wm = wid & 3, wn = wid >> 2;           // 4 m-warps x 2 n-warps
    const int brow = blockIdx.y * 128, bcol = blockIdx.x * 128;

    float acc[2][8][4];
#pragma unroll
    for (int mt = 0; mt < 2; mt++)
#pragma unroll
        for (int nt = 0; nt < 8; nt++)
#pragma unroll
            for (int c = 0; c < 4; c++) acc[mt][nt][c] = 0.f;

    const float* Ab = A + (size_t)brow * K;
    const float* Bb = B + (size_t)bcol * K;

    float4 ra[4], rb[4];
#pragma unroll
    for (int s = 0; s < 4; s++) {                    // prefetch chunk 0
        int f = t + 256 * s, row = f >> 3, c4 = (f & 7) * 4;
        ra[s] = *(const float4*)(Ab + (size_t)row * K + c4);
        rb[s] = *(const float4*)(Bb + (size_t)row * K + c4);
    }

    const int nc = K / 32;
    for (int c = 0; c < nc; c++) {
        __syncthreads();
#pragma unroll
        for (int s = 0; s < 4; s++) {
            int f = t + 256 * s, row = f >> 3, c4 = (f & 7) * 4;
            As[row][c4 + 0] = f2tf32(ra[s].x); As[row][c4 + 1] = f2tf32(ra[s].y);
            As[row][c4 + 2] = f2tf32(ra[s].z); As[row][c4 + 3] = f2tf32(ra[s].w);
            Bs[row][c4 + 0] = f2tf32(rb[s].x); Bs[row][c4 + 1] = f2tf32(rb[s].y);
            Bs[row][c4 + 2] = f2tf32(rb[s].z); Bs[row][c4 + 3] = f2tf32(rb[s].w);
        }
        __syncthreads();
        if (c + 1 < nc) {
            int k0 = (c + 1) * 32;
#pragma unroll
            for (int s = 0; s < 4; s++) {
                int f = t + 256 * s, row = f >> 3, c4 = (f & 7) * 4;
                ra[s] = *(const float4*)(Ab + (size_t)row * K + k0 + c4);
                rb[s] = *(const float4*)(Bb + (size_t)row * K + k0 + c4);
            }
        }
#pragma unroll
        for (int ks = 0; ks < 4; ks++) {
            uint32_t af[2][4], bf[8][2];
#pragma unroll
            for (int mt = 0; mt < 2; mt++) {
                int rb0 = wm * 32 + mt * 16 + gr;
                af[mt][0] = __float_as_uint(As[rb0][ks * 8 + tq]);
                af[mt][1] = __float_as_uint(As[rb0 + 8][ks * 8 + tq]);
                af[mt][2] = __float_as_uint(As[rb0][ks * 8 + tq + 4]);
                af[mt][3] = __float_as_uint(As[rb0 + 8][ks * 8 + tq + 4]);
            }
#pragma unroll
            for (int nt = 0; nt < 8; nt++) {
                int cb = wn * 64 + nt * 8 + gr;
                bf[nt][0] = __float_as_uint(Bs[cb][ks * 8 + tq]);
                bf[nt][1] = __float_as_uint(Bs[cb][ks * 8 + tq + 4]);
            }
#pragma unroll
            for (int mt = 0; mt < 2; mt++)
#pragma unroll
                for (int nt = 0; nt < 8; nt++)
                    mma_t32(acc[mt][nt], af[mt], bf[nt]);
        }
    }

#pragma unroll
    for (int mt = 0; mt < 2; mt++) {
        int r0 = brow + wm * 32 + mt * 16 + gr;
#pragma unroll
        for (int nt = 0; nt < 8; nt++) {
            int col = bcol + wn * 64 + nt * 8 + 2 * tq;
            *(float2*)(C + (size_t)r0 * ldc + col) =
                make_float2(acc[mt][nt][0], acc[mt][nt][1]);
            *(float2*)(C + (size_t)(r0 + 8) * ldc + col) =
                make_float2(acc[mt][nt][2], acc[mt][nt][3]);
        }
    }
}

// ---------------------------------------------------------------------------
// Transposed effective low-rank weights:
// WeffT[hr, d] = sum_kk W[(h*64+kk), d] * U[kk, r]
// ---------------------------------------------------------------------------
__global__ void weff_t_kernel(const float* __restrict__ Wq,
                              const float* __restrict__ Wk,
                              const float* __restrict__ U,
                              float* __restrict__ wqT,
                              float* __restrict__ wkT)
{
    int d  = blockIdx.x * blockDim.x + threadIdx.x;
    int hr = blockIdx.y;
    int h  = hr >> 5, r = hr & 31;
    float sq = 0.f, sk = 0.f;
#pragma unroll 8
    for (int kk = 0; kk < DK; kk++) {
        float u = __ldg(U + kk * RR + r);
        sq = fmaf(__ldg(Wq + (size_t)(h * DK + kk) * DD + d), u, sq);
        sk = fmaf(__ldg(Wk + (size_t)(h * DK + kk) * DD + d), u, sk);
    }
    wqT[(size_t)hr * DD + d] = sq;
    wkT[(size_t)hr * DD + d] = sk;
}

// ---------------------------------------------------------------------------
// Flash attention on HMMA tf32.
// grid (N/128, H, B), block 128 (4 warps), warp = 32 query rows (2 m-tiles).
// KV chunk = 64 keys. S=QK^T and O+=PV both via m16n8k8.
// SMEM (dynamic floats): Ks[64][36] | Vs[64][72] | Ps[4][32][68]
// ---------------------------------------------------------------------------
constexpr int ATT_SMEM_F = 64 * 36 + 64 * 72 + 4 * 32 * 68;   // 15616 floats
constexpr int ATT_SMEM_B = ATT_SMEM_F * 4;                    // 62464 bytes

__global__ __launch_bounds__(128) void attn_mma_kernel(
    const float* __restrict__ q, const float* __restrict__ k,
    const float* __restrict__ v, const float* __restrict__ mask,
    const int* __restrict__ rbt, float* __restrict__ z)
{
    extern __shared__ float smf[];
    float (*Ks)[36] = (float(*)[36])smf;                      // [64][36]
    float (*Vs)[72] = (float(*)[72])(smf + 64 * 36);          // [64][72]

    const int t = threadIdx.x, wid = t >> 5, lane = t & 31;
    const int gr = lane >> 2, tq = lane & 3;
    const int b = blockIdx.z, h = blockIdx.y;
    const int q0 = blockIdx.x * 128;
    float (*Pw)[68] = (float(*)[68])(smf + 64 * 36 + 64 * 72 + wid * 32 * 68);

    const float slope = exp2f(-0.5f * (float)(h + 1));
    const int   Ttok  = rbt[0];

    // Q fragments (scaled by 1/sqrt(dk)=0.125, tf32)
    uint32_t qa[2][4][4];                   // [mt][kstep][reg]
    int qrow[2];
#pragma unroll
    for (int mt = 0; mt < 2; mt++) {
        qrow[mt] = q0 + wid * 32 + mt * 16 + gr;
        const float* q0p = q + ((size_t)(b * NN + qrow[mt]) * HH + h) * RR;
        const float* q1p = q0p + (size_t)8 * HH * RR;
#pragma unroll
        for (int ks = 0; ks < 4; ks++) {
            qa[mt][ks][0] = u2tf32(q0p[ks * 8 + tq] * 0.125f);
            qa[mt][ks][1] = u2tf32(q1p[ks * 8 + tq] * 0.125f);
            qa[mt][ks][2] = u2tf32(q0p[ks * 8 + tq + 4] * 0.125f);
            qa[mt][ks][3] = u2tf32(q1p[ks * 8 + tq + 4] * 0.125f);
        }
    }

    float o[2][8][4];
#pragma unroll
    for (int mt = 0; mt < 2; mt++)
#pragma unroll
        for (int nt = 0; nt < 8; nt++)
#pragma unroll
            for (int c = 0; c < 4; c++) o[mt][nt][c] = 0.f;
    float mrun[2][2] = {{-1e30f, -1e30f}, {-1e30f, -1e30f}};
    float lrun[2][2] = {{0.f, 0.f}, {0.f, 0.f}};

    for (int kc = 0; kc < NN; kc += 64) {
        __syncthreads();
        // load K chunk (64x32) and V chunk (64x64), tf32-rounded
#pragma unroll
        for (int s = 0; s < 4; s++) {
            int f = t + 128 * s, row = f >> 3, c4 = (f & 7) * 4;
            float4 kv = *(const float4*)
                (k + ((size_t)(b * NN + kc + row) * HH + h) * RR + c4);
            Ks[row][c4 + 0] = f2tf32(kv.x); Ks[row][c4 + 1] = f2tf32(kv.y);
            Ks[row][c4 + 2] = f2tf32(kv.z); Ks[row][c4 + 3] = f2tf32(kv.w);
        }
#pragma unroll
        for (int s = 0; s < 8; s++) {
            int f = t + 128 * s, row = f >> 4, c4 = (f & 15) * 4;
            float4 vv = *(const float4*)
                (v + ((size_t)(b * NN + kc + row) * HH + h) * DK + c4);
            Vs[row][c4 + 0] = f2tf32(vv.x); Vs[row][c4 + 1] = f2tf32(vv.y);
            Vs[row][c4 + 2] = f2tf32(vv.z); Vs[row][c4 + 3] = f2tf32(vv.w);
        }
        __syncthreads();

        // ---- S = Q K^T  (64-key chunk, 8 n-tiles) ----
        float s[2][8][4];
#pragma unroll
        for (int mt = 0; mt < 2; mt++)
#pragma unroll
            for (int nt = 0; nt < 8; nt++)
#pragma unroll
                for (int c = 0; c < 4; c++) s[mt][nt][c] = 0.f;
#pragma unroll
        for (int ks = 0; ks < 4; ks++) {
            uint32_t bf[8][2];
#pragma unroll
            for (int nt = 0; nt < 8; nt++) {
                bf[nt][0] = __float_as_uint(Ks[nt * 8 + gr][ks * 8 + tq]);
                bf[nt][1] = __float_as_uint(Ks[nt * 8 + gr][ks * 8 + tq + 4]);
            }
#pragma unroll
            for (int mt = 0; mt < 2; mt++)
#pragma unroll
                for (int nt = 0; nt < 8; nt++)
                    mma_t32(s[mt][nt], qa[mt][ks], bf[nt]);
        }

        // ---- bias + online softmax ----
#pragma unroll
        for (int mt = 0; mt < 2; mt++) {
            const int i0 = qrow[mt], i1 = i0 + 8;
            const float adj0 = (float)(i0 + Ttok - NN);
            const float adj1 = (float)(i1 + Ttok - NN);
            const float* mr0 = mask + (size_t)i0 * NN;
            const float* mr1 = mask + (size_t)i1 * NN;
#pragma unroll
            for (int nt = 0; nt < 8; nt++) {
                int j0 = kc + nt * 8 + 2 * tq;
                float2 mk0 = *(const float2*)(mr0 + j0);
                float2 mk1 = *(const float2*)(mr1 + j0);
                float j0f = (float)j0, j1f = j0f + 1.f;
                s[mt][nt][0] += mk0.x - slope * fmaxf(j0f - adj0, 0.f);
                s[mt][nt][1] += mk0.y - slope * fmaxf(j1f - adj0, 0.f);
                s[mt][nt][2] += mk1.x - slope * fmaxf(j0f - adj1, 0.f);
                s[mt][nt][3] += mk1.y - slope * fmaxf(j1f - adj1, 0.f);
            }
            // row maxima (reduce across the quad)
            float lm0 = -1e30f, lm1 = -1e30f;
#pragma unroll
            for (int nt = 0; nt < 8; nt++) {
                lm0 = fmaxf(lm0, fmaxf(s[mt][nt][0], s[mt][nt][1]));
                lm1 = fmaxf(lm1, fmaxf(s[mt][nt][2], s[mt][nt][3]));
            }
            lm0 = fmaxf(lm0, __shfl_xor_sync(0xffffffffu, lm0, 1));
            lm0 = fmaxf(lm0, __shfl_xor_sync(0xffffffffu, lm0, 2));
            lm1 = fmaxf(lm1, __shfl_xor_sync(0xffffffffu, lm1, 1));
            lm1 = fmaxf(lm1, __shfl_xor_sync(0xffffffffu, lm1, 2));

            float mn0 = fmaxf(mrun[mt][0], lm0);
            float mn1 = fmaxf(mrun[mt][1], lm1);
            float sc0 = __expf(mrun[mt][0] - mn0);
            float sc1 = __expf(mrun[mt][1] - mn1);
            mrun[mt][0] = mn0; mrun[mt][1] = mn1;

            float ps0 = 0.f, ps1 = 0.f;
#pragma unroll
            for (int nt = 0; nt < 8; nt++) {
                float p0 = __expf(s[mt][nt][0] - mn0);
                float p1 = __expf(s[mt][nt][1] - mn0);
                float p2 = __expf(s[mt][nt][2] - mn1);
                float p3 = __expf(s[mt][nt][3] - mn1);
                ps0 += p0 + p1; ps1 += p2 + p3;
                int col = nt * 8 + 2 * tq;
                *(float2*)&Pw[mt * 16 + gr][col] =
                    make_float2(f2tf32(p0), f2tf32(p1));
                *(float2*)&Pw[mt * 16 + gr + 8][col] =
                    make_float2(f2tf32(p2), f2tf32(p3));
            }
            ps0 += __shfl_xor_sync(0xffffffffu, ps0, 1);
            ps0 += __shfl_xor_sync(0xffffffffu, ps0, 2);
            ps1 += __shfl_xor_sync(0xffffffffu, ps1, 1);
            ps1 += __shfl_xor_sync(0xffffffffu, ps1, 2);
            lrun[mt][0] = lrun[mt][0] * sc0 + ps0;
            lrun[mt][1] = lrun[mt][1] * sc1 + ps1;
#pragma unroll
            for (int nt = 0; nt < 8; nt++) {
                o[mt][nt][0] *= sc0; o[mt][nt][1] *= sc0;
                o[mt][nt][2] *= sc1; o[mt][nt][3] *= sc1;
            }
        }
        __syncwarp();

        // ---- O += P V  (K dim = 64 keys, 8 k-steps) ----
#pragma unroll
        for (int ks = 0; ks < 8; ks++) {
            uint32_t pa[2][4];
#pragma unroll
            for (int mt = 0; mt < 2; mt++) {
                pa[mt][0] = __float_as_uint(Pw[mt * 16 + gr][ks * 8 + tq]);
                pa[mt][1] = __float_as_uint(Pw[mt * 16 + gr + 8][ks * 8 + tq]);
                pa[mt][2] = __float_as_uint(Pw[mt * 16 + gr][ks * 8 + tq + 4]);
                pa[mt][3] = __float_as_uint(Pw[mt * 16 + gr + 8][ks * 8 + tq + 4]);
            }
#pragma unroll
            for (int nt = 0; nt < 8; nt++) {
                uint32_t vb[2];
                vb[0] = __float_as_uint(Vs[ks * 8 + tq][nt * 8 + gr]);
                vb[1] = __float_as_uint(Vs[ks * 8 + tq + 4][nt * 8 + gr]);
                mma_t32(o[0][nt], pa[0], vb);
                mma_t32(o[1][nt], pa[1], vb);
            }
        }
        __syncwarp();
    }

    // epilogue: normalize and store z
#pragma unroll
    for (int mt = 0; mt < 2; mt++) {
        float inv0 = 1.f / lrun[mt][0];
        float inv1 = 1.f / lrun[mt][1];
        float* z0 = z + ((size_t)(b * NN + qrow[mt]) * HH + h) * DK;
        float* z1 = z + ((size_t)(b * NN + qrow[mt] + 8) * HH + h) * DK;
#pragma unroll
        for (int nt = 0; nt < 8; nt++) {
            int d0 = nt * 8 + 2 * tq;
            *(float2*)(z0 + d0) = make_float2(o[mt][nt][0] * inv0,
                                              o[mt][nt][1] * inv0);
            *(float2*)(z1 + d0) = make_float2(o[mt][nt][2] * inv1,
                                              o[mt][nt][3] * inv1);
        }
    }
}

// ---------------------------------------------------------------------------
extern "C" void kernel_launch(void* const* d_in, const int* in_sizes, int n_in,
                              void* d_out, int out_size)
{
    const float* x    = (const float*)d_in[0];
    const float* mask = (const float*)d_in[1];
    const float* Wq   = (const float*)d_in[2];
    const float* Wk   = (const float*)d_in[3];
    const float* Wv   = (const float*)d_in[4];
    const float* U    = (const float*)d_in[5];
    const float* Wp   = (const float*)d_in[6];
    const int*   rbt  = (const int*)d_in[7];
    float* out = (float*)d_out;
    (void)in_sizes; (void)n_in; (void)out_size;

    float *wqT, *wkT, *qb, *kb, *vb, *zb;
    cudaGetSymbolAddress((void**)&wqT, g_wqT);
    cudaGetSymbolAddress((void**)&wkT, g_wkT);
    cudaGetSymbolAddress((void**)&qb, g_q);
    cudaGetSymbolAddress((void**)&kb, g_k);
    cudaGetSymbolAddress((void**)&vb, g_v);
    cudaGetSymbolAddress((void**)&zb, g_z);

    static bool attr_set = false;
    if (!attr_set) {
        cudaFuncSetAttribute(attn_mma_kernel,
                             cudaFuncAttributeMaxDynamicSharedMemorySize,
                             ATT_SMEM_B);
        attr_set = true;
    }

    // 1. effective low-rank weights (transposed, K-major)
    weff_t_kernel<<<dim3(DD / 256, HR), 256>>>(Wq, Wk, U, wqT, wkT);

    // 2. q = x @ WqT^T, k = x @ WkT^T
    mma_gemm<<<dim3(HR / 128, BN / 128), 256>>>(x, wqT, qb, DD, HR);
    mma_gemm<<<dim3(HR / 128, BN / 128), 256>>>(x, wkT, kb, DD, HR);

    // 3. v = x @ Wv^T
    mma_gemm<<<dim3(DD / 128, BN / 128), 256>>>(x, Wv, vb, DD, DD);

    // 4. flash attention (HMMA tf32)
    attn_mma_kernel<<<dim3(NN / 128, HH, BB), 128, ATT_SMEM_B>>>(
        qb, kb, vb, mask, rbt, zb);

    // 5. out = z @ Wproj^T
    mma_gemm<<<dim3(DD / 128, BN / 128), 256>>>(zb, Wp, out, DD, DD);
}

// round 7
// speedup vs baseline: 4.0302x; 1.0069x over previous
#include <cuda_runtime.h>
#include <math_constants.h>
#include <cstdint>

// Problem constants
constexpr int BB  = 2;
constexpr int NN  = 2048;
constexpr int DD  = 1024;
constexpr int HH  = 16;
constexpr int RR  = 32;
constexpr int DK  = 64;
constexpr int HR  = HH * RR;      // 512
constexpr int BN  = BB * NN;      // 4096

// Scratch (device globals; no allocation allowed)
__device__ float g_xr[BN * DD];          // tf32-rounded x
__device__ float g_wvr[DD * DD];         // tf32-rounded Wv
__device__ float g_wpr[DD * DD];         // tf32-rounded Wproj
__device__ float g_wqkT[DD * DD];        // rows 0..511: WqeffT, 512..1023: WkeffT (tf32)
__device__ float g_qk[BN * DD];          // cols 0..511 q, 512..1023 k (tf32)
__device__ float g_v[BN * DD];           // [b*n][h*DK+d] (tf32)
__device__ float g_z[BN * DD];           // [b*n][h*DK+d] (tf32)

// ---------------------------------------------------------------------------
// helpers
// ---------------------------------------------------------------------------
__device__ __forceinline__ uint32_t smem_u32(const void* p) {
    uint32_t a;
    asm("{ .reg .u64 t; cvta.to.shared.u64 t, %1; cvt.u32.u64 %0, t; }"
        : "=r"(a) : "l"(p));
    return a;
}
__device__ __forceinline__ float f2tf32(float x) {
    float y; asm("cvt.rna.tf32.f32 %0, %1;" : "=f"(y) : "f"(x)); return y;
}
__device__ __forceinline__ void cp16(uint32_t s, const void* g) {
    asm volatile("cp.async.cg.shared.global [%0], [%1], 16;"
                 :: "r"(s), "l"(g) : "memory");
}
#define CP_COMMIT() asm volatile("cp.async.commit_group;" ::: "memory")
#define CP_WAIT0()  asm volatile("cp.async.wait_group 0;" ::: "memory")
#define CP_WAIT1()  asm volatile("cp.async.wait_group 1;" ::: "memory")

// D += A(16x8,row) * B(8x8,col)   tf32 inputs, f32 accum
__device__ __forceinline__ void mma_t32(float d[4], const uint32_t a[4],
                                        const uint32_t b[2]) {
    asm volatile(
        "mma.sync.aligned.m16n8k8.row.col.f32.tf32.tf32.f32 "
        "{%0,%1,%2,%3}, {%4,%5,%6,%7}, {%8,%9}, {%0,%1,%2,%3};"
        : "+f"(d[0]), "+f"(d[1]), "+f"(d[2]), "+f"(d[3])
        : "r"(a[0]), "r"(a[1]), "r"(a[2]), "r"(a[3]), "r"(b[0]), "r"(b[1]));
}

// ---------------------------------------------------------------------------
// elementwise tf32 rounding copy
// ---------------------------------------------------------------------------
__global__ void round_kernel(const float* __restrict__ src,
                             float* __restrict__ dst, int n4)
{
    int i = blockIdx.x * blockDim.x + threadIdx.x;
    if (i < n4) {
        float4 v = ((const float4*)src)[i];
        v.x = f2tf32(v.x); v.y = f2tf32(v.y);
        v.z = f2tf32(v.z); v.w = f2tf32(v.w);
        ((float4*)dst)[i] = v;
    }
}

// ---------------------------------------------------------------------------
// Fused transposed effective low-rank weights (tf32-rounded):
// wqkT[hr,     d] = sum_kk Wq[(h*64+kk), d] * U[kk, r]
// wqkT[512+hr, d] = sum_kk Wk[(h*64+kk), d] * U[kk, r]
// ---------------------------------------------------------------------------
__global__ void weff_t_kernel(const float* __restrict__ Wq,
                              const float* __restrict__ Wk,
                              const float* __restrict__ U,
                              float* __restrict__ wqkT)
{
    int d  = blockIdx.x * blockDim.x + threadIdx.x;
    int hr = blockIdx.y;
    int h  = hr >> 5, r = hr & 31;
    float sq = 0.f, sk = 0.f;
#pragma unroll 8
    for (int kk = 0; kk < DK; kk++) {
        float u = __ldg(U + kk * RR + r);
        sq = fmaf(__ldg(Wq + (size_t)(h * DK + kk) * DD + d), u, sq);
        sk = fmaf(__ldg(Wk + (size_t)(h * DK + kk) * DD + d), u, sk);
    }
    wqkT[(size_t)hr * DD + d]        = f2tf32(sq);
    wqkT[(size_t)(HR + hr) * DD + d] = f2tf32(sk);
}

// ---------------------------------------------------------------------------
// tf32 HMMA GEMM with cp.async double buffering.
// C[M,N] = A[M,K] @ B[N,K]^T  (both K-major row-major, pre-rounded to tf32)
// grid (N/128, M/128), block 256 (8 warps), warp tile 32x64, K-chunk 32.
// ---------------------------------------------------------------------------
constexpr int GP    = 36;            // smem row pitch (floats)
constexpr int GTILE = 128 * GP;      // floats per matrix tile
constexpr int GEMM_SMEM = 2 * 2 * GTILE * 4;   // 73728 B (2 stages x (A,B))

__global__ __launch_bounds__(256, 2) void mma_gemm(
    const float* __restrict__ A, const float* __restrict__ B,
    float* __restrict__ C, int K, int ldc, int round_out)
{
    extern __shared__ float sm[];
    const uint32_t smb = smem_u32(sm);
    const int t = threadIdx.x, wid = t >> 5, lane = t & 31;
    const int gr = lane >> 2, tq = lane & 3;
    const int wm = wid & 3, wn = wid >> 2;
    const int brow = blockIdx.y * 128, bcol = blockIdx.x * 128;

    const float* Ab = A + (size_t)brow * K;
    const float* Bb = B + (size_t)bcol * K;
    const int row_l = t >> 3, c4_l = (t & 7) * 4;

    float acc[2][8][4] = {};
    const int nc = K / 32;

    // stage issue: 4 A float4 + 4 B float4 per thread
    auto issue = [&](int c) {
        const int buf = c & 1, k0 = c * 32;
        uint32_t as = smb + (uint32_t)buf * (2 * GTILE * 4);
        uint32_t bs = as + GTILE * 4;
#pragma unroll
        for (int s = 0; s < 4; s++) {
            int row = row_l + 32 * s;
            cp16(as + (row * GP + c4_l) * 4, Ab + (size_t)row * K + k0 + c4_l);
            cp16(bs + (row * GP + c4_l) * 4, Bb + (size_t)row * K + k0 + c4_l);
        }
        CP_COMMIT();
    };

    issue(0);
    for (int c = 0; c < nc; c++) {
        __syncthreads();                     // all warps done with buf (c+1)&1
        if (c + 1 < nc) { issue(c + 1); CP_WAIT1(); }
        else            { CP_WAIT0(); }
        __syncthreads();                     // stage c visible to all threads

        const float* As = sm + (c & 1) * 2 * GTILE;
        const float* Bs = As + GTILE;
#pragma unroll
        for (int ks = 0; ks < 4; ks++) {
            uint32_t af[2][4], bf[8][2];
#pragma unroll
            for (int mt = 0; mt < 2; mt++) {
                int rb0 = wm * 32 + mt * 16 + gr;
                af[mt][0] = __float_as_uint(As[rb0 * GP + ks * 8 + tq]);
                af[mt][1] = __float_as_uint(As[(rb0 + 8) * GP + ks * 8 + tq]);
                af[mt][2] = __float_as_uint(As[rb0 * GP + ks * 8 + tq + 4]);
                af[mt][3] = __float_as_uint(As[(rb0 + 8) * GP + ks * 8 + tq + 4]);
            }
#pragma unroll
            for (int nt = 0; nt < 8; nt++) {
                int cb = wn * 64 + nt * 8 + gr;
                bf[nt][0] = __float_as_uint(Bs[cb * GP + ks * 8 + tq]);
                bf[nt][1] = __float_as_uint(Bs[cb * GP + ks * 8 + tq + 4]);
            }
#pragma unroll
            for (int mt = 0; mt < 2; mt++)
#pragma unroll
                for (int nt = 0; nt < 8; nt++)
                    mma_t32(acc[mt][nt], af[mt], bf[nt]);
        }
    }

#pragma unroll
    for (int mt = 0; mt < 2; mt++) {
        int r0 = brow + wm * 32 + mt * 16 + gr;
#pragma unroll
        for (int nt = 0; nt < 8; nt++) {
            float v0 = acc[mt][nt][0], v1 = acc[mt][nt][1];
            float v2 = acc[mt][nt][2], v3 = acc[mt][nt][3];
            if (round_out) {
                v0 = f2tf32(v0); v1 = f2tf32(v1);
                v2 = f2tf32(v2); v3 = f2tf32(v3);
            }
            int col = bcol + wn * 64 + nt * 8 + 2 * tq;
            *(float2*)(C + (size_t)r0 * ldc + col) = make_float2(v0, v1);
            *(float2*)(C + (size_t)(r0 + 8) * ldc + col) = make_float2(v2, v3);
        }
    }
}

// ---------------------------------------------------------------------------
// Flash attention on HMMA tf32, cp.async double-buffered K/V.
// grid (N/128, H, B), block 128 (4 warps), warp = 32 query rows (2 m-tiles).
// KV chunk = 64 keys.
// SMEM: 2 stages x (K[64][36] + V[64][72]) + P[4][32][68] = 90112 B
// ---------------------------------------------------------------------------
constexpr int KP = 36, VP = 72, PP = 68;
constexpr int KV_STAGE_F = 64 * KP + 64 * VP;           // 6912 floats
constexpr int P_OFF_F    = 2 * KV_STAGE_F;              // 13824
constexpr int ATT_SMEM_B = (P_OFF_F + 4 * 32 * PP) * 4; // 90112 bytes

__global__ __launch_bounds__(128) void attn_mma_kernel(
    const float* __restrict__ qk, const float* __restrict__ v,
    const float* __restrict__ mask, const int* __restrict__ rbt,
    float* __restrict__ z)
{
    extern __shared__ float smf[];
    const uint32_t smb = smem_u32(smf);

    const int t = threadIdx.x, wid = t >> 5, lane = t & 31;
    const int gr = lane >> 2, tq = lane & 3;
    const int b = blockIdx.z, h = blockIdx.y;
    const int q0 = blockIdx.x * 128;
    float* Pw = smf + P_OFF_F + wid * 32 * PP;

    const float slope = exp2f(-0.5f * (float)(h + 1));
    const int   Ttok  = rbt[0];

    // Q fragments (pre-rounded tf32; *0.125 is exact)
    uint32_t qa[2][4][4];
    int qrow[2];
#pragma unroll
    for (int mt = 0; mt < 2; mt++) {
        qrow[mt] = q0 + wid * 32 + mt * 16 + gr;
        const float* q0p = qk + (size_t)(b * NN + qrow[mt]) * DD + h * RR;
        const float* q1p = q0p + (size_t)8 * DD;
#pragma unroll
        for (int ks = 0; ks < 4; ks++) {
            qa[mt][ks][0] = __float_as_uint(q0p[ks * 8 + tq] * 0.125f);
            qa[mt][ks][1] = __float_as_uint(q1p[ks * 8 + tq] * 0.125f);
            qa[mt][ks][2] = __float_as_uint(q0p[ks * 8 + tq + 4] * 0.125f);
            qa[mt][ks][3] = __float_as_uint(q1p[ks * 8 + tq + 4] * 0.125f);
        }
    }

    // stage issue: K 4 float4/thread, V 8 float4/thread
    auto issue = [&](int c) {
        const int buf = c & 1, kc = c * 64;
        uint32_t ksm = smb + (uint32_t)buf * (KV_STAGE_F * 4);
        uint32_t vsm = ksm + 64 * KP * 4;
        const float* kb = qk + (size_t)(b * NN + kc) * DD + HR + h * RR;
        const float* vb = v + (size_t)(b * NN + kc) * DD + h * DK;
#pragma unroll
        for (int s = 0; s < 4; s++) {
            int f = t + 128 * s, row = f >> 3, c4 = (f & 7) * 4;
            cp16(ksm + (row * KP + c4) * 4, kb + (size_t)row * DD + c4);
        }
#pragma unroll
        for (int s = 0; s < 8; s++) {
            int f = t + 128 * s, row = f >> 4, c4 = (f & 15) * 4;
            cp16(vsm + (row * VP + c4) * 4, vb + (size_t)row * DD + c4);
        }
        CP_COMMIT();
    };

    float o[2][8][4] = {};
    float mrun[2][2] = {{-1e30f, -1e30f}, {-1e30f, -1e30f}};
    float lrun[2][2] = {{0.f, 0.f}, {0.f, 0.f}};

    const int nch = NN / 64;
    issue(0);
    for (int c = 0; c < nch; c++) {
        const int kc = c * 64;
        __syncthreads();
        if (c + 1 < nch) { issue(c + 1); CP_WAIT1(); }
        else             { CP_WAIT0(); }
        __syncthreads();

        const float* Ks = smf + (c & 1) * KV_STAGE_F;
        const float* Vs = Ks + 64 * KP;

        // ---- S = Q K^T ----
        float s[2][8][4] = {};
#pragma unroll
        for (int ks = 0; ks < 4; ks++) {
            uint32_t bf[8][2];
#pragma unroll
            for (int nt = 0; nt < 8; nt++) {
                bf[nt][0] = __float_as_uint(Ks[(nt * 8 + gr) * KP + ks * 8 + tq]);
                bf[nt][1] = __float_as_uint(Ks[(nt * 8 + gr) * KP + ks * 8 + tq + 4]);
            }
#pragma unroll
            for (int mt = 0; mt < 2; mt++)
#pragma unroll
                for (int nt = 0; nt < 8; nt++)
                    mma_t32(s[mt][nt], qa[mt][ks], bf[nt]);
        }

        // ---- bias + online softmax ----
#pragma unroll
        for (int mt = 0; mt < 2; mt++) {
            const int i0 = qrow[mt], i1 = i0 + 8;
            const float adj0 = (float)(i0 + Ttok - NN);
            const float adj1 = (float)(i1 + Ttok - NN);
            const float* mr0 = mask + (size_t)i0 * NN;
            const float* mr1 = mask + (size_t)i1 * NN;
#pragma unroll
            for (int nt = 0; nt < 8; nt++) {
                int j0 = kc + nt * 8 + 2 * tq;
                float2 mk0 = *(const float2*)(mr0 + j0);
                float2 mk1 = *(const float2*)(mr1 + j0);
                float j0f = (float)j0, j1f = j0f + 1.f;
                s[mt][nt][0] += mk0.x - slope * fmaxf(j0f - adj0, 0.f);
                s[mt][nt][1] += mk0.y - slope * fmaxf(j1f - adj0, 0.f);
                s[mt][nt][2] += mk1.x - slope * fmaxf(j0f - adj1, 0.f);
                s[mt][nt][3] += mk1.y - slope * fmaxf(j1f - adj1, 0.f);
            }
            float lm0 = -1e30f, lm1 = -1e30f;
#pragma unroll
            for (int nt = 0; nt < 8; nt++) {
                lm0 = fmaxf(lm0, fmaxf(s[mt][nt][0], s[mt][nt][1]));
                lm1 = fmaxf(lm1, fmaxf(s[mt][nt][2], s[mt][nt][3]));
            }
            lm0 = fmaxf(lm0, __shfl_xor_sync(0xffffffffu, lm0, 1));
            lm0 = fmaxf(lm0, __shfl_xor_sync(0xffffffffu, lm0, 2));
            lm1 = fmaxf(lm1, __shfl_xor_sync(0xffffffffu, lm1, 1));
            lm1 = fmaxf(lm1, __shfl_xor_sync(0xffffffffu, lm1, 2));

            float mn0 = fmaxf(mrun[mt][0], lm0);
            float mn1 = fmaxf(mrun[mt][1], lm1);
            float sc0 = __expf(mrun[mt][0] - mn0);
            float sc1 = __expf(mrun[mt][1] - mn1);
            mrun[mt][0] = mn0; mrun[mt][1] = mn1;

            float ps0 = 0.f, ps1 = 0.f;
#pragma unroll
            for (int nt = 0; nt < 8; nt++) {
                float p0 = __expf(s[mt][nt][0] - mn0);
                float p1 = __expf(s[mt][nt][1] - mn0);
                float p2 = __expf(s[mt][nt][2] - mn1);
                float p3 = __expf(s[mt][nt][3] - mn1);
                ps0 += p0 + p1; ps1 += p2 + p3;
                int col = nt * 8 + 2 * tq;
                *(float2*)&Pw[(mt * 16 + gr) * PP + col] =
                    make_float2(f2tf32(p0), f2tf32(p1));
                *(float2*)&Pw[(mt * 16 + gr + 8) * PP + col] =
                    make_float2(f2tf32(p2), f2tf32(p3));
            }
            ps0 += __shfl_xor_sync(0xffffffffu, ps0, 1);
            ps0 += __shfl_xor_sync(0xffffffffu, ps0, 2);
            ps1 += __shfl_xor_sync(0xffffffffu, ps1, 1);
            ps1 += __shfl_xor_sync(0xffffffffu, ps1, 2);
            lrun[mt][0] = lrun[mt][0] * sc0 + ps0;
            lrun[mt][1] = lrun[mt][1] * sc1 + ps1;
#pragma unroll
            for (int nt = 0; nt < 8; nt++) {
                o[mt][nt][0] *= sc0; o[mt][nt][1] *= sc0;
                o[mt][nt][2] *= sc1; o[mt][nt][3] *= sc1;
            }
        }
        __syncwarp();

        // ---- O += P V ----
#pragma unroll
        for (int ks = 0; ks < 8; ks++) {
            uint32_t pa[2][4];
#pragma unroll
            for (int mt = 0; mt < 2; mt++) {
                pa[mt][0] = __float_as_uint(Pw[(mt * 16 + gr) * PP + ks * 8 + tq]);
                pa[mt][1] = __float_as_uint(Pw[(mt * 16 + gr + 8) * PP + ks * 8 + tq]);
                pa[mt][2] = __float_as_uint(Pw[(mt * 16 + gr) * PP + ks * 8 + tq + 4]);
                pa[mt][3] = __float_as_uint(Pw[(mt * 16 + gr + 8) * PP + ks * 8 + tq + 4]);
            }
#pragma unroll
            for (int nt = 0; nt < 8; nt++) {
                uint32_t vb[2];
                vb[0] = __float_as_uint(Vs[(ks * 8 + tq) * VP + nt * 8 + gr]);
                vb[1] = __float_as_uint(Vs[(ks * 8 + tq + 4) * VP + nt * 8 + gr]);
                mma_t32(o[0][nt], pa[0], vb);
                mma_t32(o[1][nt], pa[1], vb);
            }
        }
        __syncwarp();
    }

    // epilogue: normalize, round to tf32 (feeds proj GEMM), store z
#pragma unroll
    for (int mt = 0; mt < 2; mt++) {
        float inv0 = 1.f / lrun[mt][0];
        float inv1 = 1.f / lrun[mt][1];
        float* z0 = z + (size_t)(b * NN + qrow[mt]) * DD + h * DK;
        float* z1 = z + (size_t)(b * NN + qrow[mt] + 8) * DD + h * DK;
#pragma unroll
        for (int nt = 0; nt < 8; nt++) {
            int d0 = nt * 8 + 2 * tq;
            *(float2*)(z0 + d0) = make_float2(f2tf32(o[mt][nt][0] * inv0),
                                              f2tf32(o[mt][nt][1] * inv0));
            *(float2*)(z1 + d0) = make_float2(f2tf32(o[mt][nt][2] * inv1),
                                              f2tf32(o[mt][nt][3] * inv1));
        }
    }
}

// ---------------------------------------------------------------------------
extern "C" void kernel_launch(void* const* d_in, const int* in_sizes, int n_in,
                              void* d_out, int out_size)
{
    const float* x    = (const float*)d_in[0];
    const float* mask = (const float*)d_in[1];
    const float* Wq   = (const float*)d_in[2];
    const float* Wk   = (const float*)d_in[3];
    const float* Wv   = (const float*)d_in[4];
    const float* U    = (const float*)d_in[5];
    const float* Wp   = (const float*)d_in[6];
    const int*   rbt  = (const int*)d_in[7];
    float* out = (float*)d_out;
    (void)in_sizes; (void)n_in; (void)out_size;

    float *xr, *wvr, *wpr, *wqkT, *qkb, *vb, *zb;
    cudaGetSymbolAddress((void**)&xr, g_xr);
    cudaGetSymbolAddress((void**)&wvr, g_wvr);
    cudaGetSymbolAddress((void**)&wpr, g_wpr);
    cudaGetSymbolAddress((void**)&wqkT, g_wqkT);
    cudaGetSymbolAddress((void**)&qkb, g_qk);
    cudaGetSymbolAddress((void**)&vb, g_v);
    cudaGetSymbolAddress((void**)&zb, g_z);

    static bool attr_set = false;
    if (!attr_set) {
        cudaFuncSetAttribute(mma_gemm,
                             cudaFuncAttributeMaxDynamicSharedMemorySize,
                             GEMM_SMEM);
        cudaFuncSetAttribute(attn_mma_kernel,
                             cudaFuncAttributeMaxDynamicSharedMemorySize,
                             ATT_SMEM_B);
        attr_set = true;
    }

    // 0. pre-round GEMM inputs to tf32
    round_kernel<<<(BN * DD / 4 + 255) / 256, 256>>>(x, xr, BN * DD / 4);
    round_kernel<<<(DD * DD / 4 + 255) / 256, 256>>>(Wv, wvr, DD * DD / 4);
    round_kernel<<<(DD * DD / 4 + 255) / 256, 256>>>(Wp, wpr, DD * DD / 4);

    // 1. fused effective low-rank weights (transposed, K-major, tf32)
    weff_t_kernel<<<dim3(DD / 256, HR), 256>>>(Wq, Wk, U, wqkT);

    // 2. fused q|k = x @ wqkT^T   [4096,1024]x[1024,1024]^T, rounded outputs
    mma_gemm<<<dim3(DD / 128, BN / 128), 256, GEMM_SMEM>>>(
        xr, wqkT, qkb, DD, DD, 1);

    // 3. v = x @ Wv^T, rounded outputs
    mma_gemm<<<dim3(DD / 128, BN / 128), 256, GEMM_SMEM>>>(
        xr, wvr, vb, DD, DD, 1);

    // 4. flash attention (HMMA tf32, cp.async)
    attn_mma_kernel<<<dim3(NN / 128, HH, BB), 128, ATT_SMEM_B>>>(
        qkb, vb, mask, rbt, zb);

    // 5. out = z @ Wproj^T (full fp32 output)
    mma_gemm<<<dim3(DD / 128, BN / 128), 256, GEMM_SMEM>>>(
        zb, wpr, out, DD, DD, 0);
}

// round 8
// speedup vs baseline: 6.2629x; 1.5540x over previous
#include <cuda_runtime.h>
#include <cuda_fp16.h>
#include <math_constants.h>
#include <cstdint>

// Problem constants
constexpr int BB  = 2;
constexpr int NN  = 2048;
constexpr int DD  = 1024;
constexpr int HH  = 16;
constexpr int RR  = 32;
constexpr int DK  = 64;
constexpr int HR  = HH * RR;      // 512
constexpr int BN  = BB * NN;      // 4096

// Scratch (device globals; no allocation allowed)
__device__ __half g_xh[BN * DD];          // x in fp16
__device__ __half g_wvh[DD * DD];         // Wv fp16  [n][k]
__device__ __half g_wph[DD * DD];         // Wproj fp16 [n][k]
__device__ __half g_wqkh[DD * DD];        // rows 0..511 WqeffT, 512..1023 WkeffT
__device__ __half g_qkh[BN * DD];         // cols 0..511 q | 512..1023 k
__device__ __half g_vh[BN * DD];          // [bn][h*64+d]
__device__ __half g_vt[BB * HH * DK * NN];// [b][h][d][n]
__device__ __half g_zh[BN * DD];          // [bn][h*64+d]

// ---------------------------------------------------------------------------
// helpers
// ---------------------------------------------------------------------------
__device__ __forceinline__ uint32_t smem_u32(const void* p) {
    uint32_t a;
    asm("{ .reg .u64 t; cvta.to.shared.u64 t, %1; cvt.u32.u64 %0, t; }"
        : "=r"(a) : "l"(p));
    return a;
}
__device__ __forceinline__ void cp16(uint32_t s, const void* g) {
    asm volatile("cp.async.cg.shared.global [%0], [%1], 16;"
                 :: "r"(s), "l"(g) : "memory");
}
#define CP_COMMIT() asm volatile("cp.async.commit_group;" ::: "memory")
#define CP_WAIT0()  asm volatile("cp.async.wait_group 0;" ::: "memory")
#define CP_WAIT1()  asm volatile("cp.async.wait_group 1;" ::: "memory")

// D += A(16x16,row) * B(16x8,col)   fp16 inputs, f32 accum
__device__ __forceinline__ void mma_f16(float d[4], const uint32_t a[4],
                                        const uint32_t b[2]) {
    asm volatile(
        "mma.sync.aligned.m16n8k16.row.col.f32.f16.f16.f32 "
        "{%0,%1,%2,%3}, {%4,%5,%6,%7}, {%8,%9}, {%0,%1,%2,%3};"
        : "+f"(d[0]), "+f"(d[1]), "+f"(d[2]), "+f"(d[3])
        : "r"(a[0]), "r"(a[1]), "r"(a[2]), "r"(a[3]), "r"(b[0]), "r"(b[1]));
}
__device__ __forceinline__ uint32_t pack_h2(float a, float b) {
    __half2 h = __floats2half2_rn(a, b);
    return *(uint32_t*)&h;
}

// ---------------------------------------------------------------------------
// f32 -> f16 conversion
// ---------------------------------------------------------------------------
__global__ void tohalf_kernel(const float* __restrict__ src,
                              __half* __restrict__ dst, int n4)
{
    int i = blockIdx.x * blockDim.x + threadIdx.x;
    if (i < n4) {
        float4 v = ((const float4*)src)[i];
        uint2 o;
        o.x = pack_h2(v.x, v.y);
        o.y = pack_h2(v.z, v.w);
        ((uint2*)dst)[i] = o;
    }
}

// ---------------------------------------------------------------------------
// Effective low-rank weights -> fp16, K-major:
// wqkh[sel*512 + h*32 + r, d] = sum_kk Wsel[(h*64+kk), d] * U[kk, r]
// grid (DD/256, HH, 2), block 256
// ---------------------------------------------------------------------------
__global__ void weff_h_kernel(const float* __restrict__ Wq,
                              const float* __restrict__ Wk,
                              const float* __restrict__ U,
                              __half* __restrict__ wqkh)
{
    __shared__ float Us[DK][RR];
    const int d = blockIdx.x * 256 + threadIdx.x;
    const int h = blockIdx.y, sel = blockIdx.z;
    const float* W = sel ? Wk : Wq;
    for (int i = threadIdx.x; i < DK * RR; i += 256)
        Us[i >> 5][i & 31] = U[i];
    __syncthreads();

    float w[DK];
#pragma unroll
    for (int kk = 0; kk < DK; kk++)
        w[kk] = W[(size_t)(h * DK + kk) * DD + d];
#pragma unroll 1
    for (int r = 0; r < RR; r++) {
        float s = 0.f;
#pragma unroll
        for (int kk = 0; kk < DK; kk++) s = fmaf(w[kk], Us[kk][r], s);
        wqkh[(size_t)(sel * HR + h * RR + r) * DD + d] = __float2half(s);
    }
}

// ---------------------------------------------------------------------------
// V transpose: vh[bn][h*64+d] -> vt[b][h][d][n]
// grid (NN/64, HH, BB), block 256
// ---------------------------------------------------------------------------
__global__ void vtrans_kernel(const __half* __restrict__ vh,
                              __half* __restrict__ vt)
{
    __shared__ __half ts[64][72];
    const int b = blockIdx.z, h = blockIdx.y, n0 = blockIdx.x * 64;
    const int t = threadIdx.x;
#pragma unroll
    for (int s = 0; s < 2; s++) {
        int f = t + 256 * s, row = f >> 3, cc = (f & 7) * 8;
        *(uint4*)&ts[row][cc] =
            *(const uint4*)(vh + (size_t)(b * NN + n0 + row) * DD + h * DK + cc);
    }
    __syncthreads();
#pragma unroll
    for (int s = 0; s < 2; s++) {
        int f = t + 256 * s, dr = f >> 3, cc = (f & 7) * 8;
        __half tmp[8];
#pragma unroll
        for (int j = 0; j < 8; j++) tmp[j] = ts[cc + j][dr];
        *(uint4*)(vt + ((size_t)((b * HH + h) * DK + dr)) * NN + n0 + cc) =
            *(uint4*)tmp;
    }
}

// ---------------------------------------------------------------------------
// fp16 HMMA GEMM with cp.async double buffering.
// C[M,N] = A[M,K] @ B[N,K]^T   (A,B half, K-major)
// grid (N/128, M/128), block 256 (8 warps), warp tile 32x64, K-chunk 64.
// Output: f32 to Cf (out_half=0) or half to Ch (out_half=1).
// ---------------------------------------------------------------------------
constexpr int HP      = 72;                 // smem row pitch (halfs)
constexpr int HTILE_B = 128 * HP * 2;       // 18432 bytes
constexpr int HGEMM_SMEM = 2 * 2 * HTILE_B; // 73728

__global__ __launch_bounds__(256, 2) void hgemm(
    const __half* __restrict__ A, const __half* __restrict__ B,
    float* __restrict__ Cf, __half* __restrict__ Ch, int K, int ldc,
    int out_half)
{
    extern __shared__ char sm[];
    const uint32_t smb = smem_u32(sm);
    const int t = threadIdx.x, wid = t >> 5, lane = t & 31;
    const int gr = lane >> 2, tq = lane & 3;
    const int wm = wid & 3, wn = wid >> 2;
    const int brow = blockIdx.y * 128, bcol = blockIdx.x * 128;

    const __half* Ab = A + (size_t)brow * K;
    const __half* Bb = B + (size_t)bcol * K;
    const int row_l = t >> 3, cc_l = (t & 7) * 8;

    float acc[2][8][4] = {};
    const int nc = K / 64;

    auto issue = [&](int c) {
        const int buf = c & 1, k0 = c * 64;
        uint32_t as = smb + (uint32_t)buf * (2 * HTILE_B);
        uint32_t bs = as + HTILE_B;
#pragma unroll
        for (int s = 0; s < 4; s++) {
            int row = row_l + 32 * s;
            cp16(as + (row * HP + cc_l) * 2, Ab + (size_t)row * K + k0 + cc_l);
            cp16(bs + (row * HP + cc_l) * 2, Bb + (size_t)row * K + k0 + cc_l);
        }
        CP_COMMIT();
    };

    issue(0);
    for (int c = 0; c < nc; c++) {
        __syncthreads();
        if (c + 1 < nc) { issue(c + 1); CP_WAIT1(); }
        else            { CP_WAIT0(); }
        __syncthreads();

        const __half* As = (const __half*)(sm + (c & 1) * 2 * HTILE_B);
        const __half* Bs = (const __half*)(sm + (c & 1) * 2 * HTILE_B + HTILE_B);
#pragma unroll
        for (int ks = 0; ks < 4; ks++) {
            const int kb = ks * 16;
            uint32_t af[2][4], bf[8][2];
#pragma unroll
            for (int mt = 0; mt < 2; mt++) {
                int rb0 = wm * 32 + mt * 16 + gr;
                af[mt][0] = *(const uint32_t*)&As[rb0 * HP + kb + 2 * tq];
                af[mt][1] = *(const uint32_t*)&As[(rb0 + 8) * HP + kb + 2 * tq];
                af[mt][2] = *(const uint32_t*)&As[rb0 * HP + kb + 2 * tq + 8];
                af[mt][3] = *(const uint32_t*)&As[(rb0 + 8) * HP + kb + 2 * tq + 8];
            }
#pragma unroll
            for (int nt = 0; nt < 8; nt++) {
                int cb = wn * 64 + nt * 8 + gr;
                bf[nt][0] = *(const uint32_t*)&Bs[cb * HP + kb + 2 * tq];
                bf[nt][1] = *(const uint32_t*)&Bs[cb * HP + kb + 2 * tq + 8];
            }
#pragma unroll
            for (int mt = 0; mt < 2; mt++)
#pragma unroll
                for (int nt = 0; nt < 8; nt++)
                    mma_f16(acc[mt][nt], af[mt], bf[nt]);
        }
    }

#pragma unroll
    for (int mt = 0; mt < 2; mt++) {
        int r0 = brow + wm * 32 + mt * 16 + gr;
#pragma unroll
        for (int nt = 0; nt < 8; nt++) {
            int col = bcol + wn * 64 + nt * 8 + 2 * tq;
            if (out_half) {
                *(uint32_t*)(Ch + (size_t)r0 * ldc + col) =
                    pack_h2(acc[mt][nt][0], acc[mt][nt][1]);
                *(uint32_t*)(Ch + (size_t)(r0 + 8) * ldc + col) =
                    pack_h2(acc[mt][nt][2], acc[mt][nt][3]);
            } else {
                *(float2*)(Cf + (size_t)r0 * ldc + col) =
                    make_float2(acc[mt][nt][0], acc[mt][nt][1]);
                *(float2*)(Cf + (size_t)(r0 + 8) * ldc + col) =
                    make_float2(acc[mt][nt][2], acc[mt][nt][3]);
            }
        }
    }
}

// ---------------------------------------------------------------------------
// Flash attention, fp16 HMMA, P kept in registers (C-frag -> A-frag).
// grid (N/128, H, B), block 128 (4 warps), warp = 32 query rows (2 m-tiles).
// KV chunk = 64 keys, cp.async double buffered.
// SMEM: 2 stages x (K[64 keys][40h] + Vt[64 d][72h]) = 28672 B
// ---------------------------------------------------------------------------
constexpr int KPH = 40, VPH = 72;
constexpr int KTB = 64 * KPH * 2;        // 5120
constexpr int VTB = 64 * VPH * 2;        // 9216
constexpr int STG = KTB + VTB;           // 14336
constexpr int ATT_SMEM = 2 * STG;        // 28672

__global__ __launch_bounds__(128) void attn_h_kernel(
    const __half* __restrict__ qk, const __half* __restrict__ vt,
    const float* __restrict__ mask, const int* __restrict__ rbt,
    __half* __restrict__ z)
{
    extern __shared__ char sma[];
    const uint32_t smb = smem_u32(sma);

    const int t = threadIdx.x, wid = t >> 5, lane = t & 31;
    const int gr = lane >> 2, tq = lane & 3;
    const int b = blockIdx.z, h = blockIdx.y;
    const int q0 = blockIdx.x * 128;

    const float slope = exp2f(-0.5f * (float)(h + 1));
    const int   Ttok  = rbt[0];

    // Q fragments (raw fp16; 1/8 scale applied post-MMA)
    uint32_t qa[2][2][4];
    int qrow[2];
#pragma unroll
    for (int mt = 0; mt < 2; mt++) {
        qrow[mt] = q0 + wid * 32 + mt * 16 + gr;
        const __half* q0p = qk + (size_t)(b * NN + qrow[mt]) * DD + h * RR;
        const __half* q1p = q0p + (size_t)8 * DD;
#pragma unroll
        for (int ks = 0; ks < 2; ks++) {
            qa[mt][ks][0] = *(const uint32_t*)&q0p[ks * 16 + 2 * tq];
            qa[mt][ks][1] = *(const uint32_t*)&q1p[ks * 16 + 2 * tq];
            qa[mt][ks][2] = *(const uint32_t*)&q0p[ks * 16 + 2 * tq + 8];
            qa[mt][ks][3] = *(const uint32_t*)&q1p[ks * 16 + 2 * tq + 8];
        }
    }

    auto issue = [&](int c) {
        const int buf = c & 1, kc = c * 64;
        uint32_t ksm = smb + (uint32_t)buf * STG;
        uint32_t vsm = ksm + KTB;
        const __half* kb = qk + (size_t)(b * NN + kc) * DD + HR + h * RR;
        const __half* vb = vt + ((size_t)((b * HH + h) * DK)) * NN + kc;
#pragma unroll
        for (int s = 0; s < 2; s++) {
            int f = t + 128 * s, row = f >> 2, cc = (f & 3) * 8;
            cp16(ksm + (row * KPH + cc) * 2, kb + (size_t)row * DD + cc);
        }
#pragma unroll
        for (int s = 0; s < 4; s++) {
            int f = t + 128 * s, row = f >> 3, cc = (f & 7) * 8;
            cp16(vsm + (row * VPH + cc) * 2, vb + (size_t)row * NN + cc);
        }
        CP_COMMIT();
    };

    float o[2][8][4] = {};
    float mrun[2][2] = {{-1e30f, -1e30f}, {-1e30f, -1e30f}};
    float lrun[2][2] = {{0.f, 0.f}, {0.f, 0.f}};

    const int nch = NN / 64;
    issue(0);
    for (int c = 0; c < nch; c++) {
        const int kc = c * 64;
        __syncthreads();
        if (c + 1 < nch) { issue(c + 1); CP_WAIT1(); }
        else             { CP_WAIT0(); }
        __syncthreads();

        const __half* Ks = (const __half*)(sma + (c & 1) * STG);
        const __half* Vs = (const __half*)(sma + (c & 1) * STG + KTB);

        // ---- S = Q K^T ----
        float s[2][8][4] = {};
#pragma unroll
        for (int ks = 0; ks < 2; ks++) {
            uint32_t bf[8][2];
#pragma unroll
            for (int nt = 0; nt < 8; nt++) {
                bf[nt][0] = *(const uint32_t*)&Ks[(nt * 8 + gr) * KPH + ks * 16 + 2 * tq];
                bf[nt][1] = *(const uint32_t*)&Ks[(nt * 8 + gr) * KPH + ks * 16 + 2 * tq + 8];
            }
#pragma unroll
            for (int mt = 0; mt < 2; mt++)
#pragma unroll
                for (int nt = 0; nt < 8; nt++)
                    mma_f16(s[mt][nt], qa[mt][ks], bf[nt]);
        }

        // ---- scale + bias + online softmax + P pack ----
        uint32_t pa[2][4][4];
#pragma unroll
        for (int mt = 0; mt < 2; mt++) {
            const int i0 = qrow[mt], i1 = i0 + 8;
            const float adj0 = (float)(i0 + Ttok - NN);
            const float adj1 = (float)(i1 + Ttok - NN);
            const float* mr0 = mask + (size_t)i0 * NN;
            const float* mr1 = mask + (size_t)i1 * NN;
#pragma unroll
            for (int nt = 0; nt < 8; nt++) {
                int j0 = kc + nt * 8 + 2 * tq;
                float2 mk0 = *(const float2*)(mr0 + j0);
                float2 mk1 = *(const float2*)(mr1 + j0);
                float j0f = (float)j0, j1f = j0f + 1.f;
                s[mt][nt][0] = fmaf(s[mt][nt][0], 0.125f,
                                    mk0.x - slope * fmaxf(j0f - adj0, 0.f));
                s[mt][nt][1] = fmaf(s[mt][nt][1], 0.125f,
                                    mk0.y - slope * fmaxf(j1f - adj0, 0.f));
                s[mt][nt][2] = fmaf(s[mt][nt][2], 0.125f,
                                    mk1.x - slope * fmaxf(j0f - adj1, 0.f));
                s[mt][nt][3] = fmaf(s[mt][nt][3], 0.125f,
                                    mk1.y - slope * fmaxf(j1f - adj1, 0.f));
            }
            float lm0 = -1e30f, lm1 = -1e30f;
#pragma unroll
            for (int nt = 0; nt < 8; nt++) {
                lm0 = fmaxf(lm0, fmaxf(s[mt][nt][0], s[mt][nt][1]));
                lm1 = fmaxf(lm1, fmaxf(s[mt][nt][2], s[mt][nt][3]));
            }
            lm0 = fmaxf(lm0, __shfl_xor_sync(0xffffffffu, lm0, 1));
            lm0 = fmaxf(lm0, __shfl_xor_sync(0xffffffffu, lm0, 2));
            lm1 = fmaxf(lm1, __shfl_xor_sync(0xffffffffu, lm1, 1));
            lm1 = fmaxf(lm1, __shfl_xor_sync(0xffffffffu, lm1, 2));

            float mn0 = fmaxf(mrun[mt][0], lm0);
            float mn1 = fmaxf(mrun[mt][1], lm1);
            float sc0 = __expf(mrun[mt][0] - mn0);
            float sc1 = __expf(mrun[mt][1] - mn1);
            mrun[mt][0] = mn0; mrun[mt][1] = mn1;

            float ps0 = 0.f, ps1 = 0.f;
#pragma unroll
            for (int nt = 0; nt < 8; nt++) {
                float p0 = __expf(s[mt][nt][0] - mn0);
                float p1 = __expf(s[mt][nt][1] - mn0);
                float p2 = __expf(s[mt][nt][2] - mn1);
                float p3 = __expf(s[mt][nt][3] - mn1);
                ps0 += p0 + p1; ps1 += p2 + p3;
                // C-frag -> A-frag: keys nt*8.. map to kstep nt>>1, half nt&1
                pa[mt][nt >> 1][(nt & 1) * 2 + 0] = pack_h2(p0, p1);
                pa[mt][nt >> 1][(nt & 1) * 2 + 1] = pack_h2(p2, p3);
            }
            ps0 += __shfl_xor_sync(0xffffffffu, ps0, 1);
            ps0 += __shfl_xor_sync(0xffffffffu, ps0, 2);
            ps1 += __shfl_xor_sync(0xffffffffu, ps1, 1);
            ps1 += __shfl_xor_sync(0xffffffffu, ps1, 2);
            lrun[mt][0] = lrun[mt][0] * sc0 + ps0;
            lrun[mt][1] = lrun[mt][1] * sc1 + ps1;
#pragma unroll
            for (int nt = 0; nt < 8; nt++) {
                o[mt][nt][0] *= sc0; o[mt][nt][1] *= sc0;
                o[mt][nt][2] *= sc1; o[mt][nt][3] *= sc1;
            }
        }

        // ---- O += P V  (Vt rows = d, cols = keys) ----
#pragma unroll
        for (int ks = 0; ks < 4; ks++) {
            uint32_t bf[8][2];
#pragma unroll
            for (int nt = 0; nt < 8; nt++) {
                bf[nt][0] = *(const uint32_t*)&Vs[(nt * 8 + gr) * VPH + ks * 16 + 2 * tq];
                bf[nt][1] = *(const uint32_t*)&Vs[(nt * 8 + gr) * VPH + ks * 16 + 2 * tq + 8];
            }
#pragma unroll
            for (int mt = 0; mt < 2; mt++)
#pragma unroll
                for (int nt = 0; nt < 8; nt++)
                    mma_f16(o[mt][nt], pa[mt][ks], bf[nt]);
        }
    }

    // epilogue: normalize, store z (fp16, feeds proj GEMM)
#pragma unroll
    for (int mt = 0; mt < 2; mt++) {
        float inv0 = 1.f / lrun[mt][0];
        float inv1 = 1.f / lrun[mt][1];
        __half* z0 = z + (size_t)(b * NN + qrow[mt]) * DD + h * DK;
        __half* z1 = z0 + (size_t)8 * DD;
#pragma unroll
        for (int nt = 0; nt < 8; nt++) {
            int d0 = nt * 8 + 2 * tq;
            *(uint32_t*)(z0 + d0) = pack_h2(o[mt][nt][0] * inv0,
                                            o[mt][nt][1] * inv0);
            *(uint32_t*)(z1 + d0) = pack_h2(o[mt][nt][2] * inv1,
                                            o[mt][nt][3] * inv1);
        }
    }
}

// ---------------------------------------------------------------------------
extern "C" void kernel_launch(void* const* d_in, const int* in_sizes, int n_in,
                              void* d_out, int out_size)
{
    const float* x    = (const float*)d_in[0];
    const float* mask = (const float*)d_in[1];
    const float* Wq   = (const float*)d_in[2];
    const float* Wk   = (const float*)d_in[3];
    const float* Wv   = (const float*)d_in[4];
    const float* U    = (const float*)d_in[5];
    const float* Wp   = (const float*)d_in[6];
    const int*   rbt  = (const int*)d_in[7];
    float* out = (float*)d_out;
    (void)in_sizes; (void)n_in; (void)out_size;

    __half *xh, *wvh, *wph, *wqkh, *qkh, *vh, *vt, *zh;
    cudaGetSymbolAddress((void**)&xh, g_xh);
    cudaGetSymbolAddress((void**)&wvh, g_wvh);
    cudaGetSymbolAddress((void**)&wph, g_wph);
    cudaGetSymbolAddress((void**)&wqkh, g_wqkh);
    cudaGetSymbolAddress((void**)&qkh, g_qkh);
    cudaGetSymbolAddress((void**)&vh, g_vh);
    cudaGetSymbolAddress((void**)&vt, g_vt);
    cudaGetSymbolAddress((void**)&zh, g_zh);

    static bool attr_set = false;
    if (!attr_set) {
        cudaFuncSetAttribute(hgemm,
                             cudaFuncAttributeMaxDynamicSharedMemorySize,
                             HGEMM_SMEM);
        attr_set = true;
    }

    // 0. convert inputs to fp16
    tohalf_kernel<<<(BN * DD / 4 + 255) / 256, 256>>>(x, xh, BN * DD / 4);
    tohalf_kernel<<<(DD * DD / 4 + 255) / 256, 256>>>(Wv, wvh, DD * DD / 4);
    tohalf_kernel<<<(DD * DD / 4 + 255) / 256, 256>>>(Wp, wph, DD * DD / 4);

    // 1. effective low-rank weights (fp16, K-major, q|k fused)
    weff_h_kernel<<<dim3(DD / 256, HH, 2), 256>>>(Wq, Wk, U, wqkh);

    // 2. q|k = x @ wqk^T  -> fp16
    hgemm<<<dim3(DD / 128, BN / 128), 256, HGEMM_SMEM>>>(
        xh, wqkh, nullptr, qkh, DD, DD, 1);

    // 3. v = x @ Wv^T -> fp16, then transpose to [b][h][d][n]
    hgemm<<<dim3(DD / 128, BN / 128), 256, HGEMM_SMEM>>>(
        xh, wvh, nullptr, vh, DD, DD, 1);
    vtrans_kernel<<<dim3(NN / 64, HH, BB), 256>>>(vh, vt);

    // 4. flash attention (fp16 HMMA, register-resident P)
    attn_h_kernel<<<dim3(NN / 128, HH, BB), 128, ATT_SMEM>>>(
        qkh, vt, mask, rbt, zh);

    // 5. out = z @ Wproj^T (f32 output)
    hgemm<<<dim3(DD / 128, BN / 128), 256, HGEMM_SMEM>>>(
        zh, wph, out, nullptr, DD, DD, 0);
}